// round 1
// baseline (speedup 1.0000x reference)
#include <cuda_runtime.h>
#include <cstddef>

#define DIM      1024
#define HEADS    16
#define HEAD_DIM 64
#define BLK      32
#define FEAT     128
#define BATCH    4
#define SEQ      4096
#define NBLK     (SEQ / BLK)      // 128
#define ROWS     (BATCH * SEQ)    // 16384

// Scratch (allocation-free rule: __device__ globals)
__device__ float g_qkv[(size_t)ROWS * 3 * DIM];   // 192 MB
__device__ float g_attn[(size_t)ROWS * DIM];      // 64 MB

// ---------------------------------------------------------------------------
// SGEMM: C[M,N] = A[M,K] @ B[K,N] (+ bias). 128x128 tile, BK=16, 8x8 microtile.
// All dims are multiples of 128/16 here, so no bounds checks.
// ---------------------------------------------------------------------------
template<bool BIAS>
__global__ __launch_bounds__(256)
void sgemm128(const float* __restrict__ A, const float* __restrict__ B,
              const float* __restrict__ bias, float* __restrict__ C,
              int M, int N, int K)
{
    __shared__ float As[16][128];   // transposed: As[k][m]
    __shared__ float Bs[16][128];

    const int tid = threadIdx.x;
    const int bm = blockIdx.y, bn = blockIdx.x;
    const int tx = tid & 15, ty = tid >> 4;

    const float* Aptr = A + (size_t)bm * 128 * K;
    const float* Bptr = B + (size_t)bn * 128;

    float acc[8][8];
#pragma unroll
    for (int i = 0; i < 8; i++)
#pragma unroll
        for (int j = 0; j < 8; j++) acc[i][j] = 0.0f;

    const int a_row0 = tid >> 2;   // 0..63, +64 for second vec
    const int a_c4   = tid & 3;    // which float4 in the 16-wide row
    const int b_row0 = tid >> 5;   // 0..7, +8 for second vec
    const int b_c4   = tid & 31;

    for (int kt = 0; kt < K; kt += 16) {
#pragma unroll
        for (int i = 0; i < 2; i++) {
            int row = a_row0 + i * 64;
            float4 a4 = *(const float4*)(Aptr + (size_t)row * K + kt + a_c4 * 4);
            As[a_c4 * 4 + 0][row] = a4.x;
            As[a_c4 * 4 + 1][row] = a4.y;
            As[a_c4 * 4 + 2][row] = a4.z;
            As[a_c4 * 4 + 3][row] = a4.w;
        }
#pragma unroll
        for (int i = 0; i < 2; i++) {
            int row = b_row0 + i * 8;
            *(float4*)(&Bs[row][b_c4 * 4]) =
                *(const float4*)(Bptr + (size_t)(kt + row) * N + b_c4 * 4);
        }
        __syncthreads();

#pragma unroll
        for (int k = 0; k < 16; k++) {
            float a[8], bb[8];
            *(float4*)(a)      = *(const float4*)(&As[k][ty * 8]);
            *(float4*)(a + 4)  = *(const float4*)(&As[k][ty * 8 + 4]);
            *(float4*)(bb)     = *(const float4*)(&Bs[k][tx * 8]);
            *(float4*)(bb + 4) = *(const float4*)(&Bs[k][tx * 8 + 4]);
#pragma unroll
            for (int i = 0; i < 8; i++)
#pragma unroll
                for (int j = 0; j < 8; j++)
                    acc[i][j] += a[i] * bb[j];
        }
        __syncthreads();
    }

    float bv[8];
#pragma unroll
    for (int j = 0; j < 8; j++)
        bv[j] = BIAS ? bias[bn * 128 + tx * 8 + j] : 0.0f;

#pragma unroll
    for (int i = 0; i < 8; i++) {
        int row = bm * 128 + ty * 8 + i;
        float* crow = C + (size_t)row * N + bn * 128 + tx * 8;
        float4 v0, v1;
        v0.x = acc[i][0] + bv[0]; v0.y = acc[i][1] + bv[1];
        v0.z = acc[i][2] + bv[2]; v0.w = acc[i][3] + bv[3];
        v1.x = acc[i][4] + bv[4]; v1.y = acc[i][5] + bv[5];
        v1.z = acc[i][6] + bv[6]; v1.w = acc[i][7] + bv[7];
        *(float4*)(crow)     = v0;
        *(float4*)(crow + 4) = v1;
    }
}

// ---------------------------------------------------------------------------
// Fused middle: per (b, h, m) block of 32 tokens:
//   qf = elu(q @ proj_h) + 1 ; kf = elu(k @ proj_h) + 1
//   kv = kf^T @ v ; ksum = sum_s kf ; z = 1/(qf . ksum + eps)
//   attn_block = (qf @ kv) * z   -> written in [b, n, h*64+d] layout
// Dynamic smem 91008 B; proj buffer is reused for the kv state.
// ---------------------------------------------------------------------------
#define SQF_STRIDE 129   // padded to avoid bank conflicts in z / ksum phases
#define MID_SMEM_FLOATS (14336 + 2 * (32 * SQF_STRIDE) + 128 + 32)   // 22752
#define MID_SMEM_BYTES  (MID_SMEM_FLOATS * 4)                        // 91008

__global__ __launch_bounds__(256)
void middle_kernel(const float* __restrict__ qkv, const float* __restrict__ proj,
                   float* __restrict__ attn)
{
    extern __shared__ float sm[];
    float* sq    = sm;                    // 2048  q[32][64]
    float* sk    = sm + 2048;             // 2048  k[32][64]
    float* sv    = sm + 4096;             // 2048  v[32][64]
    float* sp    = sm + 6144;             // 8192  proj_h[64][128]  (aliased below)
    float* skv   = sp;                    // 8192  kv[128][64] (after proj is dead)
    float* sqf   = sm + 14336;            // 32*129
    float* skf   = sqf + 32 * SQF_STRIDE; // 32*129
    float* sksum = skf + 32 * SQF_STRIDE; // 128
    float* sz    = sksum + 128;           // 32

    const int t = threadIdx.x;
    const int gb = blockIdx.x;
    const int b = gb / (HEADS * NBLK);
    const int rem = gb - b * (HEADS * NBLK);
    const int h = rem / NBLK;
    const int m = rem - h * NBLK;

    // ---- load q/k/v (32x64 each) and proj_h (64x128), float4 coalesced ----
    const float* base = qkv + ((size_t)(b * SEQ + m * BLK)) * (3 * DIM) + h * HEAD_DIM;
    for (int v4 = t; v4 < 512; v4 += 256) {
        int s = v4 >> 4, c = v4 & 15;
        const float* r = base + (size_t)s * (3 * DIM) + c * 4;
        ((float4*)sq)[v4] = *(const float4*)(r);
        ((float4*)sk)[v4] = *(const float4*)(r + DIM);
        ((float4*)sv)[v4] = *(const float4*)(r + 2 * DIM);
    }
    const float* ph = proj + (size_t)h * HEAD_DIM * FEAT;
    for (int v4 = t; v4 < 2048; v4 += 256)
        ((float4*)sp)[v4] = ((const float4*)ph)[v4];
    __syncthreads();

    // ---- phase B: qf/kf = elu(x @ proj)+1, 4x4 register blocking ----
    {
        const int tS = t >> 5;    // warp id 0..7 -> s base
        const int tF = t & 31;    // lane -> f base
        float qa[4][4], ka[4][4];
#pragma unroll
        for (int i = 0; i < 4; i++)
#pragma unroll
            for (int j = 0; j < 4; j++) { qa[i][j] = 0.0f; ka[i][j] = 0.0f; }

        for (int d = 0; d < HEAD_DIM; d++) {
            float qv[4], kv_[4], pv[4];
#pragma unroll
            for (int i = 0; i < 4; i++) {
                qv[i]  = sq[(tS + 8 * i) * 64 + d];
                kv_[i] = sk[(tS + 8 * i) * 64 + d];
            }
#pragma unroll
            for (int j = 0; j < 4; j++)
                pv[j] = sp[d * 128 + tF + 32 * j];
#pragma unroll
            for (int i = 0; i < 4; i++)
#pragma unroll
                for (int j = 0; j < 4; j++) {
                    qa[i][j] += qv[i] * pv[j];
                    ka[i][j] += kv_[i] * pv[j];
                }
        }
#pragma unroll
        for (int i = 0; i < 4; i++) {
            int s = tS + 8 * i;
#pragma unroll
            for (int j = 0; j < 4; j++) {
                int f = tF + 32 * j;
                float x = qa[i][j];
                sqf[s * SQF_STRIDE + f] = (x > 0.0f) ? (x + 1.0f) : __expf(x);
                x = ka[i][j];
                skf[s * SQF_STRIDE + f] = (x > 0.0f) ? (x + 1.0f) : __expf(x);
            }
        }
    }
    __syncthreads();

    // ---- phase C: kv[f][d] = sum_s kf[s][f] * v[s][d] ; ksum ----
    {
        const int tF = t >> 3;   // 0..31 -> f in {tF, tF+32, tF+64, tF+96}
        const int tD = t & 7;    // d in {tD, tD+8, ..., tD+56}
        float kva[4][8];
#pragma unroll
        for (int j = 0; j < 4; j++)
#pragma unroll
            for (int i = 0; i < 8; i++) kva[j][i] = 0.0f;

        for (int s = 0; s < BLK; s++) {
            float kfv[4], vv[8];
#pragma unroll
            for (int j = 0; j < 4; j++) kfv[j] = skf[s * SQF_STRIDE + tF + 32 * j];
#pragma unroll
            for (int i = 0; i < 8; i++) vv[i] = sv[s * 64 + tD + 8 * i];
#pragma unroll
            for (int j = 0; j < 4; j++)
#pragma unroll
                for (int i = 0; i < 8; i++)
                    kva[j][i] += kfv[j] * vv[i];
        }
        if (t < FEAT) {
            float acc = 0.0f;
            for (int s = 0; s < BLK; s++) acc += skf[s * SQF_STRIDE + t];
            sksum[t] = acc;
        }
#pragma unroll
        for (int j = 0; j < 4; j++)
#pragma unroll
            for (int i = 0; i < 8; i++)
                skv[(tF + 32 * j) * 64 + tD + 8 * i] = kva[j][i];
    }
    __syncthreads();

    // ---- z[s] = 1/(qf[s,:] . ksum + eps) ----
    if (t < BLK) {
        float acc = 0.0f;
        for (int f = 0; f < FEAT; f++) acc += sqf[t * SQF_STRIDE + f] * sksum[f];
        sz[t] = 1.0f / (acc + 1e-8f);
    }
    __syncthreads();

    // ---- phase D: out[s][d] = z[s] * sum_f qf[s][f] * kv[f][d] ----
    {
        const int tS = t >> 5;     // warp id -> s base
        const int lane = t & 31;   // d = lane + 32*j
        float oa[4][2];
#pragma unroll
        for (int i = 0; i < 4; i++) { oa[i][0] = 0.0f; oa[i][1] = 0.0f; }

        for (int f = 0; f < FEAT; f++) {
            float qv[4], kvv[2];
#pragma unroll
            for (int i = 0; i < 4; i++) qv[i] = sqf[(tS + 8 * i) * SQF_STRIDE + f];
            kvv[0] = skv[f * 64 + lane];
            kvv[1] = skv[f * 64 + lane + 32];
#pragma unroll
            for (int i = 0; i < 4; i++) {
                oa[i][0] += qv[i] * kvv[0];
                oa[i][1] += qv[i] * kvv[1];
            }
        }
        const int rowbase = b * SEQ + m * BLK;
#pragma unroll
        for (int i = 0; i < 4; i++) {
            int s = tS + 8 * i;
            float zz = sz[s];
            float* orow = attn + (size_t)(rowbase + s) * DIM + h * HEAD_DIM;
            orow[lane]      = oa[i][0] * zz;
            orow[lane + 32] = oa[i][1] * zz;
        }
    }
}

// ---------------------------------------------------------------------------
extern "C" void kernel_launch(void* const* d_in, const int* in_sizes, int n_in,
                              void* d_out, int out_size)
{
    const float* x    = (const float*)d_in[0];
    const float* Wqkv = (const float*)d_in[1];
    const float* proj = (const float*)d_in[2];
    const float* Wout = (const float*)d_in[3];
    const float* bout = (const float*)d_in[4];
    float* out = (float*)d_out;

    float* qkv;  cudaGetSymbolAddress((void**)&qkv, g_qkv);
    float* attn; cudaGetSymbolAddress((void**)&attn, g_attn);

    cudaFuncSetAttribute(middle_kernel,
                         cudaFuncAttributeMaxDynamicSharedMemorySize,
                         MID_SMEM_BYTES);

    // 1) qkv = x @ Wqkv            [16384,1024] @ [1024,3072]
    sgemm128<false><<<dim3((3 * DIM) / 128, ROWS / 128), 256>>>(
        x, Wqkv, nullptr, qkv, ROWS, 3 * DIM, DIM);

    // 2) fused per-block linear attention
    middle_kernel<<<BATCH * HEADS * NBLK, 256, MID_SMEM_BYTES>>>(qkv, proj, attn);

    // 3) out = attn @ Wout + bout  [16384,1024] @ [1024,1024]
    sgemm128<true><<<dim3(DIM / 128, ROWS / 128), 256>>>(
        attn, Wout, bout, out, ROWS, DIM, DIM);
}

// round 4
// speedup vs baseline: 1.2862x; 1.2862x over previous
#include <cuda_runtime.h>
#include <cstdint>
#include <cstddef>

#define DIM      1024
#define HEADS    16
#define HEAD_DIM 64
#define BLK      32
#define FEAT     128
#define BATCH    4
#define SEQ      4096
#define NBLK     (SEQ / BLK)      // 128
#define ROWS     (BATCH * SEQ)    // 16384

// Scratch (allocation-free rule: __device__ globals)
__device__ float g_qkv[(size_t)ROWS * 3 * DIM];                 // 192 MB
__device__ float g_attn[(size_t)ROWS * DIM];                    // 64 MB
__device__ float g_wt[(size_t)3 * DIM * DIM + (size_t)DIM * DIM]; // 16 MB

// ---------------------------------------------------------------------------
// helpers
// ---------------------------------------------------------------------------
__device__ __forceinline__ uint32_t smem_u32(const void* p) {
    uint32_t a;
    asm("{ .reg .u64 t; cvta.to.shared.u64 t, %1; cvt.u32.u64 %0, t; }" : "=r"(a) : "l"(p));
    return a;
}

#define SW128(off) ((off) ^ (((off) >> 3) & 0x70))

#define CP16(dst, src) \
    asm volatile("cp.async.cg.shared.global [%0], [%1], 16;" :: "r"(dst), "l"(src) : "memory")
#define CP_COMMIT() asm volatile("cp.async.commit_group;" ::: "memory")
#define CP_WAIT2()  asm volatile("cp.async.wait_group 2;" ::: "memory")

#define LDSM4(r0, r1, r2, r3, addr)                                           \
    asm volatile("ldmatrix.sync.aligned.m8n8.x4.shared.b16 {%0,%1,%2,%3}, [%4];" \
                 : "=r"(r0), "=r"(r1), "=r"(r2), "=r"(r3) : "r"(addr))

#define MMA_TF32(d, a0, a1, a2, a3, b0, b1)                                   \
    asm volatile("mma.sync.aligned.m16n8k8.row.col.f32.tf32.tf32.f32 "        \
                 "{%0,%1,%2,%3}, {%4,%5,%6,%7}, {%8,%9}, {%0,%1,%2,%3};"      \
                 : "+f"((d)[0]), "+f"((d)[1]), "+f"((d)[2]), "+f"((d)[3])     \
                 : "r"(a0), "r"(a1), "r"(a2), "r"(a3), "r"(b0), "r"(b1))

// tf32x3 split: hi = rn(tf32(x)), lo = rn(tf32(x - hi)). Dropped lo*lo ~ eps^2.
__device__ __forceinline__ void tf32_split(uint32_t v, uint32_t& hi, uint32_t& lo) {
    float f = __uint_as_float(v);
    asm("cvt.rna.tf32.f32 %0, %1;" : "=r"(hi) : "f"(f));
    float r = f - __uint_as_float(hi);
    asm("cvt.rna.tf32.f32 %0, %1;" : "=r"(lo) : "f"(r));
}

// ---------------------------------------------------------------------------
// tf32x3 mma.sync GEMM: C[M,N] = A[M,K] @ Bt[N,K]^T (+bias), fp32-accurate.
// CTA 128x128, BK=32 (128B rows, SW128), 8 warps (4Mx2N, warp 32x64),
// 4-stage cp.async pipeline. Per product: hi*hi + lo*hi + hi*lo.
// ---------------------------------------------------------------------------
#define BM 128
#define BN 128
#define BK 32
#define NSTAGE 4
#define A_ST (BM * 128)            // 16384 B
#define B_ST (BN * 128)            // 16384 B
#define ST_BYTES (A_ST + B_ST)     // 32768 B
#define G_SMEM (NSTAGE * ST_BYTES) // 131072 B

template<bool BIAS>
__global__ __launch_bounds__(256)
void tc_gemm(const float* __restrict__ A, const float* __restrict__ Bt,
             const float* __restrict__ bias, float* __restrict__ C,
             int M, int N, int K)
{
    extern __shared__ char smem[];
    const uint32_t sbase = smem_u32(smem);
    const int t = threadIdx.x;
    const int lid = t & 31, wid = t >> 5;
    const int wm = wid & 3, wn = wid >> 2;       // warp grid 4(M) x 2(N)
    const int m0 = wm * 32, n0 = wn * 64;        // warp tile origin
    const int bn = blockIdx.x, bm = blockIdx.y;
    const int NK = K / BK;

    const float* Abase = A  + (size_t)bm * BM * K;
    const float* Bbase = Bt + (size_t)bn * BN * K;

    // producer mapping: 8 threads per 128B row
    const int prow = t >> 3;
    const int pc4  = t & 7;

    auto load_stage = [&](int s, int kc) {
        const uint32_t sa = sbase + s * ST_BYTES;
        const uint32_t sb = sa + A_ST;
        const int koff = kc * BK;
#pragma unroll
        for (int i = 0; i < 4; i++) {
            int row = prow + i * 32;
            uint32_t off = SW128((uint32_t)(row * 128 + pc4 * 16));
            CP16(sa + off, Abase + (size_t)row * K + koff + pc4 * 4);
        }
#pragma unroll
        for (int i = 0; i < 4; i++) {
            int row = prow + i * 32;
            uint32_t off = SW128((uint32_t)(row * 128 + pc4 * 16));
            CP16(sb + off, Bbase + (size_t)row * K + koff + pc4 * 4);
        }
        CP_COMMIT();
    };

    // ldmatrix per-thread base offsets (bytes, pre-swizzle)
    const int lr = lid & 15;
    const int lk16 = (lid >> 4) * 16;
    const uint32_t aoff = (uint32_t)((m0 + lr) * 128 + lk16);
    uint32_t boff[4];
#pragma unroll
    for (int j = 0; j < 4; j++)
        boff[j] = (uint32_t)((n0 + 16 * j + lr) * 128 + lk16);

    float acc[2][8][4];
#pragma unroll
    for (int mi = 0; mi < 2; mi++)
#pragma unroll
        for (int f = 0; f < 8; f++)
#pragma unroll
            for (int r = 0; r < 4; r++) acc[mi][f][r] = 0.0f;

    // prologue
    for (int s = 0; s < NSTAGE - 1; s++) load_stage(s, s);

    for (int it = 0; it < NK; it++) {
        CP_WAIT2();
        __syncthreads();
        const int nxt = it + NSTAGE - 1;
        if (nxt < NK) load_stage(nxt & 3, nxt);

        const uint32_t sa = sbase + (it & 3) * ST_BYTES;
        const uint32_t sb = sa + A_ST;

#pragma unroll
        for (int ks = 0; ks < 4; ks++) {
            const uint32_t kb = ks * 32;
            uint32_t a0[4], a1[4];
            {
                uint32_t ad0 = sa + SW128(aoff + kb);
                uint32_t ad1 = sa + SW128(aoff + 16 * 128 + kb);
                LDSM4(a0[0], a0[1], a0[2], a0[3], ad0);
                LDSM4(a1[0], a1[1], a1[2], a1[3], ad1);
            }
            uint32_t a0h[4], a0l[4], a1h[4], a1l[4];
#pragma unroll
            for (int r = 0; r < 4; r++) {
                tf32_split(a0[r], a0h[r], a0l[r]);
                tf32_split(a1[r], a1h[r], a1l[r]);
            }
#pragma unroll
            for (int j = 0; j < 4; j++) {
                uint32_t b[4], bh[4], bl[4];
                uint32_t bd = sb + SW128(boff[j] + kb);
                LDSM4(b[0], b[1], b[2], b[3], bd);
#pragma unroll
                for (int r = 0; r < 4; r++) tf32_split(b[r], bh[r], bl[r]);

                // b[0],b[2] -> n8 frag (n0+16j); b[1],b[3] -> (n0+16j+8)
                float* d00 = acc[0][2 * j + 0];
                float* d01 = acc[0][2 * j + 1];
                float* d10 = acc[1][2 * j + 0];
                float* d11 = acc[1][2 * j + 1];

                // hi*hi
                MMA_TF32(d00, a0h[0], a0h[1], a0h[2], a0h[3], bh[0], bh[2]);
                MMA_TF32(d01, a0h[0], a0h[1], a0h[2], a0h[3], bh[1], bh[3]);
                MMA_TF32(d10, a1h[0], a1h[1], a1h[2], a1h[3], bh[0], bh[2]);
                MMA_TF32(d11, a1h[0], a1h[1], a1h[2], a1h[3], bh[1], bh[3]);
                // lo*hi
                MMA_TF32(d00, a0l[0], a0l[1], a0l[2], a0l[3], bh[0], bh[2]);
                MMA_TF32(d01, a0l[0], a0l[1], a0l[2], a0l[3], bh[1], bh[3]);
                MMA_TF32(d10, a1l[0], a1l[1], a1l[2], a1l[3], bh[0], bh[2]);
                MMA_TF32(d11, a1l[0], a1l[1], a1l[2], a1l[3], bh[1], bh[3]);
                // hi*lo
                MMA_TF32(d00, a0h[0], a0h[1], a0h[2], a0h[3], bl[0], bl[2]);
                MMA_TF32(d01, a0h[0], a0h[1], a0h[2], a0h[3], bl[1], bl[3]);
                MMA_TF32(d10, a1h[0], a1h[1], a1h[2], a1h[3], bl[0], bl[2]);
                MMA_TF32(d11, a1h[0], a1h[1], a1h[2], a1h[3], bl[1], bl[3]);
            }
        }
        __syncthreads();
    }

    // epilogue
    const int g = lid >> 2, tq = lid & 3;
#pragma unroll
    for (int mi = 0; mi < 2; mi++) {
        int rowl = m0 + mi * 16 + g;
#pragma unroll
        for (int f = 0; f < 8; f++) {
            int col = n0 + f * 8 + tq * 2;
            float b0 = 0.0f, b1 = 0.0f;
            if (BIAS) { b0 = bias[bn * BN + col]; b1 = bias[bn * BN + col + 1]; }
            float* p0 = C + (size_t)(bm * BM + rowl) * N + bn * BN + col;
            float* p1 = C + (size_t)(bm * BM + rowl + 8) * N + bn * BN + col;
            float2 v0 = { acc[mi][f][0] + b0, acc[mi][f][1] + b1 };
            float2 v1 = { acc[mi][f][2] + b0, acc[mi][f][3] + b1 };
            *(float2*)p0 = v0;
            *(float2*)p1 = v1;
        }
    }
}

// ---------------------------------------------------------------------------
// Transpose: out[c][r] = in[r][c]. in [R,C] -> out [C,R]. block (32,8).
// ---------------------------------------------------------------------------
__global__ void transpose_k(const float* __restrict__ in, float* __restrict__ out,
                            int R, int C)
{
    __shared__ float tile[32][33];
    int bx = blockIdx.x * 32, by = blockIdx.y * 32;
#pragma unroll
    for (int i = 0; i < 32; i += 8)
        tile[threadIdx.y + i][threadIdx.x] =
            in[(size_t)(by + threadIdx.y + i) * C + bx + threadIdx.x];
    __syncthreads();
#pragma unroll
    for (int i = 0; i < 32; i += 8)
        out[(size_t)(bx + threadIdx.y + i) * R + by + threadIdx.x] =
            tile[threadIdx.x][threadIdx.y + i];
}

// ---------------------------------------------------------------------------
// Fused middle: per (b,h,m) 32-token block linear attention (unchanged, R1)
// ---------------------------------------------------------------------------
#define SQF_STRIDE 129
#define MID_SMEM_FLOATS (14336 + 2 * (32 * SQF_STRIDE) + 128 + 32)
#define MID_SMEM_BYTES  (MID_SMEM_FLOATS * 4)

__global__ __launch_bounds__(256)
void middle_kernel(const float* __restrict__ qkv, const float* __restrict__ proj,
                   float* __restrict__ attn)
{
    extern __shared__ float sm[];
    float* sq    = sm;
    float* sk    = sm + 2048;
    float* sv    = sm + 4096;
    float* sp    = sm + 6144;
    float* skv   = sp;
    float* sqf   = sm + 14336;
    float* skf   = sqf + 32 * SQF_STRIDE;
    float* sksum = skf + 32 * SQF_STRIDE;
    float* sz    = sksum + 128;

    const int t = threadIdx.x;
    const int gb = blockIdx.x;
    const int b = gb / (HEADS * NBLK);
    const int rem = gb - b * (HEADS * NBLK);
    const int h = rem / NBLK;
    const int m = rem - h * NBLK;

    const float* base = qkv + ((size_t)(b * SEQ + m * BLK)) * (3 * DIM) + h * HEAD_DIM;
    for (int v4 = t; v4 < 512; v4 += 256) {
        int s = v4 >> 4, c = v4 & 15;
        const float* r = base + (size_t)s * (3 * DIM) + c * 4;
        ((float4*)sq)[v4] = *(const float4*)(r);
        ((float4*)sk)[v4] = *(const float4*)(r + DIM);
        ((float4*)sv)[v4] = *(const float4*)(r + 2 * DIM);
    }
    const float* ph = proj + (size_t)h * HEAD_DIM * FEAT;
    for (int v4 = t; v4 < 2048; v4 += 256)
        ((float4*)sp)[v4] = ((const float4*)ph)[v4];
    __syncthreads();

    {
        const int tS = t >> 5;
        const int tF = t & 31;
        float qa[4][4], ka[4][4];
#pragma unroll
        for (int i = 0; i < 4; i++)
#pragma unroll
            for (int j = 0; j < 4; j++) { qa[i][j] = 0.0f; ka[i][j] = 0.0f; }

        for (int d = 0; d < HEAD_DIM; d++) {
            float qv[4], kv_[4], pv[4];
#pragma unroll
            for (int i = 0; i < 4; i++) {
                qv[i]  = sq[(tS + 8 * i) * 64 + d];
                kv_[i] = sk[(tS + 8 * i) * 64 + d];
            }
#pragma unroll
            for (int j = 0; j < 4; j++)
                pv[j] = sp[d * 128 + tF + 32 * j];
#pragma unroll
            for (int i = 0; i < 4; i++)
#pragma unroll
                for (int j = 0; j < 4; j++) {
                    qa[i][j] += qv[i] * pv[j];
                    ka[i][j] += kv_[i] * pv[j];
                }
        }
#pragma unroll
        for (int i = 0; i < 4; i++) {
            int s = tS + 8 * i;
#pragma unroll
            for (int j = 0; j < 4; j++) {
                int f = tF + 32 * j;
                float x = qa[i][j];
                sqf[s * SQF_STRIDE + f] = (x > 0.0f) ? (x + 1.0f) : __expf(x);
                x = ka[i][j];
                skf[s * SQF_STRIDE + f] = (x > 0.0f) ? (x + 1.0f) : __expf(x);
            }
        }
    }
    __syncthreads();

    {
        const int tF = t >> 3;
        const int tD = t & 7;
        float kva[4][8];
#pragma unroll
        for (int j = 0; j < 4; j++)
#pragma unroll
            for (int i = 0; i < 8; i++) kva[j][i] = 0.0f;

        for (int s = 0; s < BLK; s++) {
            float kfv[4], vv[8];
#pragma unroll
            for (int j = 0; j < 4; j++) kfv[j] = skf[s * SQF_STRIDE + tF + 32 * j];
#pragma unroll
            for (int i = 0; i < 8; i++) vv[i] = sv[s * 64 + tD + 8 * i];
#pragma unroll
            for (int j = 0; j < 4; j++)
#pragma unroll
                for (int i = 0; i < 8; i++)
                    kva[j][i] += kfv[j] * vv[i];
        }
        if (t < FEAT) {
            float acc = 0.0f;
            for (int s = 0; s < BLK; s++) acc += skf[s * SQF_STRIDE + t];
            sksum[t] = acc;
        }
#pragma unroll
        for (int j = 0; j < 4; j++)
#pragma unroll
            for (int i = 0; i < 8; i++)
                skv[(tF + 32 * j) * 64 + tD + 8 * i] = kva[j][i];
    }
    __syncthreads();

    if (t < BLK) {
        float acc = 0.0f;
        for (int f = 0; f < FEAT; f++) acc += sqf[t * SQF_STRIDE + f] * sksum[f];
        sz[t] = 1.0f / (acc + 1e-8f);
    }
    __syncthreads();

    {
        const int tS = t >> 5;
        const int lane = t & 31;
        float oa[4][2];
#pragma unroll
        for (int i = 0; i < 4; i++) { oa[i][0] = 0.0f; oa[i][1] = 0.0f; }

        for (int f = 0; f < FEAT; f++) {
            float qv[4], kvv[2];
#pragma unroll
            for (int i = 0; i < 4; i++) qv[i] = sqf[(tS + 8 * i) * SQF_STRIDE + f];
            kvv[0] = skv[f * 64 + lane];
            kvv[1] = skv[f * 64 + lane + 32];
#pragma unroll
            for (int i = 0; i < 4; i++) {
                oa[i][0] += qv[i] * kvv[0];
                oa[i][1] += qv[i] * kvv[1];
            }
        }
        const int rowbase = b * SEQ + m * BLK;
#pragma unroll
        for (int i = 0; i < 4; i++) {
            int s = tS + 8 * i;
            float zz = sz[s];
            float* orow = attn + (size_t)(rowbase + s) * DIM + h * HEAD_DIM;
            orow[lane]      = oa[i][0] * zz;
            orow[lane + 32] = oa[i][1] * zz;
        }
    }
}

// ---------------------------------------------------------------------------
extern "C" void kernel_launch(void* const* d_in, const int* in_sizes, int n_in,
                              void* d_out, int out_size)
{
    const float* x    = (const float*)d_in[0];
    const float* Wqkv = (const float*)d_in[1];
    const float* proj = (const float*)d_in[2];
    const float* Wout = (const float*)d_in[3];
    const float* bout = (const float*)d_in[4];
    float* out = (float*)d_out;

    float* qkv;  cudaGetSymbolAddress((void**)&qkv, g_qkv);
    float* attn; cudaGetSymbolAddress((void**)&attn, g_attn);
    float* wt;   cudaGetSymbolAddress((void**)&wt, g_wt);
    float* wqkvT = wt;                              // [3072, 1024]
    float* woutT = wt + (size_t)3 * DIM * DIM;      // [1024, 1024]

    cudaFuncSetAttribute(middle_kernel, cudaFuncAttributeMaxDynamicSharedMemorySize,
                         MID_SMEM_BYTES);
    cudaFuncSetAttribute(tc_gemm<false>, cudaFuncAttributeMaxDynamicSharedMemorySize,
                         G_SMEM);
    cudaFuncSetAttribute(tc_gemm<true>, cudaFuncAttributeMaxDynamicSharedMemorySize,
                         G_SMEM);

    // 0) transpose weights to [N, K]
    transpose_k<<<dim3((3 * DIM) / 32, DIM / 32), dim3(32, 8)>>>(Wqkv, wqkvT, DIM, 3 * DIM);
    transpose_k<<<dim3(DIM / 32, DIM / 32), dim3(32, 8)>>>(Wout, woutT, DIM, DIM);

    // 1) qkv = x @ Wqkv  (tf32x3 mma.sync)
    tc_gemm<false><<<dim3((3 * DIM) / BN, ROWS / BM), 256, G_SMEM>>>(
        x, wqkvT, nullptr, qkv, ROWS, 3 * DIM, DIM);

    // 2) fused per-block linear attention
    middle_kernel<<<BATCH * HEADS * NBLK, 256, MID_SMEM_BYTES>>>(qkv, proj, attn);

    // 3) out = attn @ Wout + bout  (tf32x3 mma.sync)
    tc_gemm<true><<<dim3(DIM / BN, ROWS / BM), 256, G_SMEM>>>(
        attn, woutT, bout, out, ROWS, DIM, DIM);
}

// round 5
// speedup vs baseline: 2.0623x; 1.6034x over previous
#include <cuda_runtime.h>
#include <cuda_fp16.h>
#include <cstdint>
#include <cstddef>

#define DIM      1024
#define HEADS    16
#define HEAD_DIM 64
#define BLK      32
#define FEAT     128
#define BATCH    4
#define SEQ      4096
#define NBLK     (SEQ / BLK)      // 128
#define ROWS     (BATCH * SEQ)    // 16384

// Scratch (allocation-free rule: __device__ globals)
__device__ float  g_qkv[(size_t)ROWS * 3 * DIM];     // 192 MB fp32
__device__ __half g_xh[(size_t)ROWS * DIM];          // 32 MB
__device__ __half g_xl[(size_t)ROWS * DIM];          // 32 MB
__device__ __half g_ah[(size_t)ROWS * DIM];          // 32 MB (attn hi)
__device__ __half g_al[(size_t)ROWS * DIM];          // 32 MB (attn lo)
__device__ __half g_wqh[(size_t)3 * DIM * DIM];      // 6 MB  (WqkvT hi)
__device__ __half g_wql[(size_t)3 * DIM * DIM];      // 6 MB
__device__ __half g_woh[(size_t)DIM * DIM];          // 2 MB  (WoutT hi)
__device__ __half g_wol[(size_t)DIM * DIM];          // 2 MB

// ---------------------------------------------------------------------------
// helpers
// ---------------------------------------------------------------------------
__device__ __forceinline__ uint32_t smem_u32(const void* p) {
    uint32_t a;
    asm("{ .reg .u64 t; cvta.to.shared.u64 t, %1; cvt.u32.u64 %0, t; }" : "=r"(a) : "l"(p));
    return a;
}

#define SW128(off) ((off) ^ (((off) >> 3) & 0x70))

#define CP16(dst, src) \
    asm volatile("cp.async.cg.shared.global [%0], [%1], 16;" :: "r"(dst), "l"(src) : "memory")
#define CP_COMMIT() asm volatile("cp.async.commit_group;" ::: "memory")
#define CP_WAIT1()  asm volatile("cp.async.wait_group 1;" ::: "memory")

#define LDSM4(r0, r1, r2, r3, addr)                                           \
    asm volatile("ldmatrix.sync.aligned.m8n8.x4.shared.b16 {%0,%1,%2,%3}, [%4];" \
                 : "=r"(r0), "=r"(r1), "=r"(r2), "=r"(r3) : "r"(addr))

#define MMA_F16(d, a0, a1, a2, a3, b0, b1)                                    \
    asm volatile("mma.sync.aligned.m16n8k16.row.col.f32.f16.f16.f32 "         \
                 "{%0,%1,%2,%3}, {%4,%5,%6,%7}, {%8,%9}, {%0,%1,%2,%3};"      \
                 : "+f"((d)[0]), "+f"((d)[1]), "+f"((d)[2]), "+f"((d)[3])     \
                 : "r"(a0), "r"(a1), "r"(a2), "r"(a3), "r"(b0), "r"(b1))

// fp16x3 split: hi = rn_f16(x), lo = rn_f16(x - hi). Residual ~2^-24 |x|.
__device__ __forceinline__ void f16_split(float x, __half& hi, __half& lo) {
    hi = __float2half_rn(x);
    lo = __float2half_rn(x - __half2float(hi));
}

// ---------------------------------------------------------------------------
// fp16x3 mma.sync GEMM: C[M,N] = A[M,K] @ Bt[N,K]^T (+bias), fp32-accurate.
// A, B pre-split into hi/lo fp16 arrays. CTA 128x128, BK=64 (128B rows, SW128),
// 8 warps (4Mx2N, warp 32x64), 3-stage cp.async pipeline.
// Per product: Ah*Bh + Al*Bh + Ah*Bl (dropped Al*Bl ~ 2^-24).
// ---------------------------------------------------------------------------
#define BM 128
#define BN 128
#define BKH 64
#define NSTAGE 3
#define TILE_B (BM * 128)          // 16384 B per operand tile
#define ST_BYTES (4 * TILE_B)      // 65536 B (Ah, Al, Bh, Bl)
#define G_SMEM (NSTAGE * ST_BYTES) // 196608 B

template<bool BIAS>
__global__ __launch_bounds__(256)
void hgemm(const __half* __restrict__ Ah, const __half* __restrict__ Al,
           const __half* __restrict__ Bh, const __half* __restrict__ Bl,
           const float* __restrict__ bias, float* __restrict__ C,
           int M, int N, int K)
{
    extern __shared__ char smem[];
    const uint32_t sbase = smem_u32(smem);
    const int t = threadIdx.x;
    const int lid = t & 31, wid = t >> 5;
    const int wm = wid & 3, wn = wid >> 2;       // warp grid 4(M) x 2(N)
    const int m0 = wm * 32, n0 = wn * 64;
    const int bn = blockIdx.x, bm = blockIdx.y;
    const int NK = K / BKH;

    const __half* Ahb = Ah + (size_t)bm * BM * K;
    const __half* Alb = Al + (size_t)bm * BM * K;
    const __half* Bhb = Bh + (size_t)bn * BN * K;
    const __half* Blb = Bl + (size_t)bn * BN * K;

    // producer: 8 threads per 128B row (8 fp16 per 16B chunk)
    const int prow = t >> 3;      // 0..31
    const int pch  = t & 7;

    auto load_stage = [&](int s, int kc) {
        const uint32_t sb0 = sbase + s * ST_BYTES;
        const int koff = kc * BKH;
#pragma unroll
        for (int i = 0; i < 4; i++) {
            int row = prow + i * 32;
            uint32_t off = SW128((uint32_t)(row * 128 + pch * 16));
            size_t g = (size_t)row * K + koff + pch * 8;
            CP16(sb0 + off,              Ahb + g);
            CP16(sb0 + TILE_B + off,     Alb + g);
            CP16(sb0 + 2 * TILE_B + off, Bhb + g);
            CP16(sb0 + 3 * TILE_B + off, Blb + g);
        }
        CP_COMMIT();
    };

    // ldmatrix per-thread base offsets (bytes, pre-swizzle)
    const int lr = lid & 15;
    const int lk16 = (lid >> 4) * 16;
    const uint32_t aoff = (uint32_t)((m0 + lr) * 128 + lk16);
    uint32_t boff[4];
#pragma unroll
    for (int j = 0; j < 4; j++)
        boff[j] = (uint32_t)((n0 + 16 * j + lr) * 128 + lk16);

    float acc[2][8][4];
#pragma unroll
    for (int mi = 0; mi < 2; mi++)
#pragma unroll
        for (int f = 0; f < 8; f++)
#pragma unroll
            for (int r = 0; r < 4; r++) acc[mi][f][r] = 0.0f;

    // prologue: 2 stages
    load_stage(0, 0);
    load_stage(1, 1);

    for (int it = 0; it < NK; it++) {
        CP_WAIT1();
        __syncthreads();
        const int nxt = it + 2;
        if (nxt < NK) load_stage(nxt % NSTAGE, nxt);

        const uint32_t s0 = sbase + (it % NSTAGE) * ST_BYTES;
        const uint32_t sAh = s0;
        const uint32_t sAl = s0 + TILE_B;
        const uint32_t sBh = s0 + 2 * TILE_B;
        const uint32_t sBl = s0 + 3 * TILE_B;

#pragma unroll
        for (int ks = 0; ks < 4; ks++) {
            const uint32_t kb = ks * 32;   // 16 fp16 = 32 bytes per k16 step
            uint32_t ah0[4], ah1[4], al0[4], al1[4];
            {
                uint32_t o0 = SW128(aoff + kb);
                uint32_t o1 = SW128(aoff + 16 * 128 + kb);
                LDSM4(ah0[0], ah0[1], ah0[2], ah0[3], sAh + o0);
                LDSM4(ah1[0], ah1[1], ah1[2], ah1[3], sAh + o1);
                LDSM4(al0[0], al0[1], al0[2], al0[3], sAl + o0);
                LDSM4(al1[0], al1[1], al1[2], al1[3], sAl + o1);
            }
#pragma unroll
            for (int j = 0; j < 4; j++) {
                uint32_t bh[4], bl[4];
                uint32_t ob = SW128(boff[j] + kb);
                LDSM4(bh[0], bh[1], bh[2], bh[3], sBh + ob);
                LDSM4(bl[0], bl[1], bl[2], bl[3], sBl + ob);

                float* d00 = acc[0][2 * j + 0];
                float* d01 = acc[0][2 * j + 1];
                float* d10 = acc[1][2 * j + 0];
                float* d11 = acc[1][2 * j + 1];

                // hi*hi
                MMA_F16(d00, ah0[0], ah0[1], ah0[2], ah0[3], bh[0], bh[2]);
                MMA_F16(d01, ah0[0], ah0[1], ah0[2], ah0[3], bh[1], bh[3]);
                MMA_F16(d10, ah1[0], ah1[1], ah1[2], ah1[3], bh[0], bh[2]);
                MMA_F16(d11, ah1[0], ah1[1], ah1[2], ah1[3], bh[1], bh[3]);
                // lo*hi
                MMA_F16(d00, al0[0], al0[1], al0[2], al0[3], bh[0], bh[2]);
                MMA_F16(d01, al0[0], al0[1], al0[2], al0[3], bh[1], bh[3]);
                MMA_F16(d10, al1[0], al1[1], al1[2], al1[3], bh[0], bh[2]);
                MMA_F16(d11, al1[0], al1[1], al1[2], al1[3], bh[1], bh[3]);
                // hi*lo
                MMA_F16(d00, ah0[0], ah0[1], ah0[2], ah0[3], bl[0], bl[2]);
                MMA_F16(d01, ah0[0], ah0[1], ah0[2], ah0[3], bl[1], bl[3]);
                MMA_F16(d10, ah1[0], ah1[1], ah1[2], ah1[3], bl[0], bl[2]);
                MMA_F16(d11, ah1[0], ah1[1], ah1[2], ah1[3], bl[1], bl[3]);
            }
        }
        __syncthreads();
    }

    // epilogue
    const int g = lid >> 2, tq = lid & 3;
#pragma unroll
    for (int mi = 0; mi < 2; mi++) {
        int rowl = m0 + mi * 16 + g;
#pragma unroll
        for (int f = 0; f < 8; f++) {
            int col = n0 + f * 8 + tq * 2;
            float b0 = 0.0f, b1 = 0.0f;
            if (BIAS) { b0 = bias[bn * BN + col]; b1 = bias[bn * BN + col + 1]; }
            float* p0 = C + (size_t)(bm * BM + rowl) * N + bn * BN + col;
            float* p1 = C + (size_t)(bm * BM + rowl + 8) * N + bn * BN + col;
            float2 v0 = { acc[mi][f][0] + b0, acc[mi][f][1] + b1 };
            float2 v1 = { acc[mi][f][2] + b0, acc[mi][f][3] + b1 };
            *(float2*)p0 = v0;
            *(float2*)p1 = v1;
        }
    }
}

// ---------------------------------------------------------------------------
// Split fp32 -> (hi, lo) fp16 arrays, elementwise (float4 vectorized).
// ---------------------------------------------------------------------------
__global__ void split_kernel(const float* __restrict__ in, __half* __restrict__ h,
                             __half* __restrict__ l, int n4)
{
    int i = blockIdx.x * blockDim.x + threadIdx.x;
    if (i >= n4) return;
    float4 v = ((const float4*)in)[i];
    __half h0, h1, h2, h3, l0, l1, l2, l3;
    f16_split(v.x, h0, l0); f16_split(v.y, h1, l1);
    f16_split(v.z, h2, l2); f16_split(v.w, h3, l3);
    ((__half2*)h)[2 * i]     = __halves2half2(h0, h1);
    ((__half2*)h)[2 * i + 1] = __halves2half2(h2, h3);
    ((__half2*)l)[2 * i]     = __halves2half2(l0, l1);
    ((__half2*)l)[2 * i + 1] = __halves2half2(l2, l3);
}

// ---------------------------------------------------------------------------
// Transpose + split: in fp32 [R,C] -> out_h/out_l fp16 [C,R]. block (32,8).
// ---------------------------------------------------------------------------
__global__ void transpose_split(const float* __restrict__ in,
                                __half* __restrict__ oh, __half* __restrict__ ol,
                                int R, int C)
{
    __shared__ float tile[32][33];
    int bx = blockIdx.x * 32, by = blockIdx.y * 32;
#pragma unroll
    for (int i = 0; i < 32; i += 8)
        tile[threadIdx.y + i][threadIdx.x] =
            in[(size_t)(by + threadIdx.y + i) * C + bx + threadIdx.x];
    __syncthreads();
#pragma unroll
    for (int i = 0; i < 32; i += 8) {
        float v = tile[threadIdx.x][threadIdx.y + i];
        __half hv, lv;
        f16_split(v, hv, lv);
        size_t idx = (size_t)(bx + threadIdx.y + i) * R + by + threadIdx.x;
        oh[idx] = hv;
        ol[idx] = lv;
    }
}

// ---------------------------------------------------------------------------
// Fused middle: per (b,h,m) 32-token block linear attention.
// Epilogue now writes attn as split fp16 hi/lo (GEMM2 operand format).
// ---------------------------------------------------------------------------
#define SQF_STRIDE 129
#define MID_SMEM_FLOATS (14336 + 2 * (32 * SQF_STRIDE) + 128 + 32)
#define MID_SMEM_BYTES  (MID_SMEM_FLOATS * 4)

__global__ __launch_bounds__(256)
void middle_kernel(const float* __restrict__ qkv, const float* __restrict__ proj,
                   __half* __restrict__ attn_h, __half* __restrict__ attn_l)
{
    extern __shared__ float sm[];
    float* sq    = sm;
    float* sk    = sm + 2048;
    float* sv    = sm + 4096;
    float* sp    = sm + 6144;
    float* skv   = sp;
    float* sqf   = sm + 14336;
    float* skf   = sqf + 32 * SQF_STRIDE;
    float* sksum = skf + 32 * SQF_STRIDE;
    float* sz    = sksum + 128;

    const int t = threadIdx.x;
    const int gb = blockIdx.x;
    const int b = gb / (HEADS * NBLK);
    const int rem = gb - b * (HEADS * NBLK);
    const int h = rem / NBLK;
    const int m = rem - h * NBLK;

    const float* base = qkv + ((size_t)(b * SEQ + m * BLK)) * (3 * DIM) + h * HEAD_DIM;
    for (int v4 = t; v4 < 512; v4 += 256) {
        int s = v4 >> 4, c = v4 & 15;
        const float* r = base + (size_t)s * (3 * DIM) + c * 4;
        ((float4*)sq)[v4] = *(const float4*)(r);
        ((float4*)sk)[v4] = *(const float4*)(r + DIM);
        ((float4*)sv)[v4] = *(const float4*)(r + 2 * DIM);
    }
    const float* ph = proj + (size_t)h * HEAD_DIM * FEAT;
    for (int v4 = t; v4 < 2048; v4 += 256)
        ((float4*)sp)[v4] = ((const float4*)ph)[v4];
    __syncthreads();

    {
        const int tS = t >> 5;
        const int tF = t & 31;
        float qa[4][4], ka[4][4];
#pragma unroll
        for (int i = 0; i < 4; i++)
#pragma unroll
            for (int j = 0; j < 4; j++) { qa[i][j] = 0.0f; ka[i][j] = 0.0f; }

        for (int d = 0; d < HEAD_DIM; d++) {
            float qv[4], kv_[4], pv[4];
#pragma unroll
            for (int i = 0; i < 4; i++) {
                qv[i]  = sq[(tS + 8 * i) * 64 + d];
                kv_[i] = sk[(tS + 8 * i) * 64 + d];
            }
#pragma unroll
            for (int j = 0; j < 4; j++)
                pv[j] = sp[d * 128 + tF + 32 * j];
#pragma unroll
            for (int i = 0; i < 4; i++)
#pragma unroll
                for (int j = 0; j < 4; j++) {
                    qa[i][j] += qv[i] * pv[j];
                    ka[i][j] += kv_[i] * pv[j];
                }
        }
#pragma unroll
        for (int i = 0; i < 4; i++) {
            int s = tS + 8 * i;
#pragma unroll
            for (int j = 0; j < 4; j++) {
                int f = tF + 32 * j;
                float x = qa[i][j];
                sqf[s * SQF_STRIDE + f] = (x > 0.0f) ? (x + 1.0f) : __expf(x);
                x = ka[i][j];
                skf[s * SQF_STRIDE + f] = (x > 0.0f) ? (x + 1.0f) : __expf(x);
            }
        }
    }
    __syncthreads();

    {
        const int tF = t >> 3;
        const int tD = t & 7;
        float kva[4][8];
#pragma unroll
        for (int j = 0; j < 4; j++)
#pragma unroll
            for (int i = 0; i < 8; i++) kva[j][i] = 0.0f;

        for (int s = 0; s < BLK; s++) {
            float kfv[4], vv[8];
#pragma unroll
            for (int j = 0; j < 4; j++) kfv[j] = skf[s * SQF_STRIDE + tF + 32 * j];
#pragma unroll
            for (int i = 0; i < 8; i++) vv[i] = sv[s * 64 + tD + 8 * i];
#pragma unroll
            for (int j = 0; j < 4; j++)
#pragma unroll
                for (int i = 0; i < 8; i++)
                    kva[j][i] += kfv[j] * vv[i];
        }
        if (t < FEAT) {
            float acc = 0.0f;
            for (int s = 0; s < BLK; s++) acc += skf[s * SQF_STRIDE + t];
            sksum[t] = acc;
        }
#pragma unroll
        for (int j = 0; j < 4; j++)
#pragma unroll
            for (int i = 0; i < 8; i++)
                skv[(tF + 32 * j) * 64 + tD + 8 * i] = kva[j][i];
    }
    __syncthreads();

    if (t < BLK) {
        float acc = 0.0f;
        for (int f = 0; f < FEAT; f++) acc += sqf[t * SQF_STRIDE + f] * sksum[f];
        sz[t] = 1.0f / (acc + 1e-8f);
    }
    __syncthreads();

    {
        const int tS = t >> 5;
        const int lane = t & 31;
        float oa[4][2];
#pragma unroll
        for (int i = 0; i < 4; i++) { oa[i][0] = 0.0f; oa[i][1] = 0.0f; }

        for (int f = 0; f < FEAT; f++) {
            float qv[4], kvv[2];
#pragma unroll
            for (int i = 0; i < 4; i++) qv[i] = sqf[(tS + 8 * i) * SQF_STRIDE + f];
            kvv[0] = skv[f * 64 + lane];
            kvv[1] = skv[f * 64 + lane + 32];
#pragma unroll
            for (int i = 0; i < 4; i++) {
                oa[i][0] += qv[i] * kvv[0];
                oa[i][1] += qv[i] * kvv[1];
            }
        }
        const int rowbase = b * SEQ + m * BLK;
#pragma unroll
        for (int i = 0; i < 4; i++) {
            int s = tS + 8 * i;
            float zz = sz[s];
            size_t off = (size_t)(rowbase + s) * DIM + h * HEAD_DIM;
            float v0 = oa[i][0] * zz;
            float v1 = oa[i][1] * zz;
            __half h0, l0, h1, l1;
            f16_split(v0, h0, l0);
            f16_split(v1, h1, l1);
            attn_h[off + lane]      = h0;
            attn_l[off + lane]      = l0;
            attn_h[off + lane + 32] = h1;
            attn_l[off + lane + 32] = l1;
        }
    }
}

// ---------------------------------------------------------------------------
extern "C" void kernel_launch(void* const* d_in, const int* in_sizes, int n_in,
                              void* d_out, int out_size)
{
    const float* x    = (const float*)d_in[0];
    const float* Wqkv = (const float*)d_in[1];
    const float* proj = (const float*)d_in[2];
    const float* Wout = (const float*)d_in[3];
    const float* bout = (const float*)d_in[4];
    float* out = (float*)d_out;

    float*  qkv; cudaGetSymbolAddress((void**)&qkv, g_qkv);
    __half *xh, *xl, *ah, *al, *wqh, *wql, *woh, *wol;
    cudaGetSymbolAddress((void**)&xh,  g_xh);
    cudaGetSymbolAddress((void**)&xl,  g_xl);
    cudaGetSymbolAddress((void**)&ah,  g_ah);
    cudaGetSymbolAddress((void**)&al,  g_al);
    cudaGetSymbolAddress((void**)&wqh, g_wqh);
    cudaGetSymbolAddress((void**)&wql, g_wql);
    cudaGetSymbolAddress((void**)&woh, g_woh);
    cudaGetSymbolAddress((void**)&wol, g_wol);

    cudaFuncSetAttribute(middle_kernel, cudaFuncAttributeMaxDynamicSharedMemorySize,
                         MID_SMEM_BYTES);
    cudaFuncSetAttribute(hgemm<false>, cudaFuncAttributeMaxDynamicSharedMemorySize,
                         G_SMEM);
    cudaFuncSetAttribute(hgemm<true>, cudaFuncAttributeMaxDynamicSharedMemorySize,
                         G_SMEM);

    // 0) operand prep: split x; transpose+split weights
    {
        int n4 = ROWS * DIM / 4;
        split_kernel<<<(n4 + 255) / 256, 256>>>(x, xh, xl, n4);
    }
    transpose_split<<<dim3((3 * DIM) / 32, DIM / 32), dim3(32, 8)>>>(Wqkv, wqh, wql, DIM, 3 * DIM);
    transpose_split<<<dim3(DIM / 32, DIM / 32), dim3(32, 8)>>>(Wout, woh, wol, DIM, DIM);

    // 1) qkv = x @ Wqkv  (fp16x3 mma.sync)
    hgemm<false><<<dim3((3 * DIM) / BN, ROWS / BM), 256, G_SMEM>>>(
        xh, xl, wqh, wql, nullptr, qkv, ROWS, 3 * DIM, DIM);

    // 2) fused per-block linear attention (writes split fp16 attn)
    middle_kernel<<<BATCH * HEADS * NBLK, 256, MID_SMEM_BYTES>>>(qkv, proj, ah, al);

    // 3) out = attn @ Wout + bout  (fp16x3 mma.sync)
    hgemm<true><<<dim3(DIM / BN, ROWS / BM), 256, G_SMEM>>>(
        ah, al, woh, wol, bout, out, ROWS, DIM, DIM);
}